// round 11
// baseline (speedup 1.0000x reference)
#include <cuda_runtime.h>
#include <cstdint>

// B=4, P2=64, TOPK=16, W2=49, C_KV=512
// r_idx: int32 (B, P2, TOPK)    [JAX x64-off emits int32]
// kv:    float32 (B, P2, W2, C_KV)
// out:   float32 (B, P2, TOPK, W2, C_KV)
//
// All-TMA direct gather, double-depth: block = (half 0..1, region 0..4095).
// Each block bulk-loads TWO 25088B chunks on ONE mbarrier (expect_tx = 2x),
// waits once, then issues TWO bulk stores back-to-back. Doubles per-CTA
// write concurrency vs R10 and halves block count; 4 CTAs/SM keeps ~200KB
// of TMA writes in flight per SM.

#define B_    4
#define P2_   64
#define TOPK_ 16
#define W2_   49
#define CKV_  512

#define N_REGIONS     (B_ * P2_ * TOPK_)        // 4096
#define REGION_BYTES  (W2_ * CKV_ * 4)          // 100352
#define HALF_BYTES    (REGION_BYTES / 2)        // 50176
#define CHUNK_BYTES   (REGION_BYTES / 4)        // 25088

__device__ __forceinline__ uint32_t smem_u32(const void* p) {
    return (uint32_t)__cvta_generic_to_shared(p);
}

__global__ void __launch_bounds__(32) kv_gather_kernel(
    const int*  __restrict__ r_idx,
    const char* __restrict__ kv,
    char*       __restrict__ out)
{
    __shared__ alignas(128) char s_data[2][CHUNK_BYTES];
    __shared__ alignas(8) unsigned long long s_mbar;

    if (threadIdx.x != 0) return;

    const int half   = blockIdx.x;              // 0..1
    const int region = blockIdx.y;              // 0..4095
    const int b = region >> 10;                 // region / (P2*TOPK)

    int r = __ldg(&r_idx[region]);
    r = min(max(r, 0), P2_ - 1);

    const uint32_t mbar  = smem_u32(&s_mbar);
    const uint32_t sdat0 = smem_u32(s_data[0]);
    const uint32_t sdat1 = smem_u32(s_data[1]);
    const long long hoff = (long long)half * HALF_BYTES;

    const char* gsrc = kv  + (long long)(b * P2_ + r) * REGION_BYTES + hoff;
    char*       gdst = out + (long long)region * REGION_BYTES + hoff;

    // -- two bulk loads on one mbarrier --
    asm volatile("mbarrier.init.shared.b64 [%0], 1;" :: "r"(mbar) : "memory");
    asm volatile("fence.proxy.async.shared::cta;" ::: "memory");
    asm volatile("mbarrier.arrive.expect_tx.shared.b64 _, [%0], %1;"
                 :: "r"(mbar), "r"((uint32_t)HALF_BYTES) : "memory");
    asm volatile(
        "cp.async.bulk.shared::cluster.global.mbarrier::complete_tx::bytes "
        "[%0], [%1], %2, [%3];"
        :: "r"(sdat0), "l"(gsrc), "r"((uint32_t)CHUNK_BYTES), "r"(mbar)
        : "memory");
    asm volatile(
        "cp.async.bulk.shared::cluster.global.mbarrier::complete_tx::bytes "
        "[%0], [%1], %2, [%3];"
        :: "r"(sdat1), "l"(gsrc + CHUNK_BYTES), "r"((uint32_t)CHUNK_BYTES), "r"(mbar)
        : "memory");

    // wait (phase 0)
    {
        uint32_t done = 0;
        do {
            asm volatile(
                "{\n\t.reg .pred p;\n\t"
                "mbarrier.try_wait.parity.shared.b64 p, [%1], 0;\n\t"
                "selp.b32 %0, 1, 0, p;\n\t}"
                : "=r"(done) : "r"(mbar) : "memory");
        } while (!done);
    }

    // -- two bulk stores back-to-back --
    asm volatile(
        "cp.async.bulk.global.shared::cta.bulk_group [%0], [%1], %2;"
        :: "l"(gdst), "r"(sdat0), "r"((uint32_t)CHUNK_BYTES)
        : "memory");
    asm volatile(
        "cp.async.bulk.global.shared::cta.bulk_group [%0], [%1], %2;"
        :: "l"(gdst + CHUNK_BYTES), "r"(sdat1), "r"((uint32_t)CHUNK_BYTES)
        : "memory");
    asm volatile("cp.async.bulk.commit_group;" ::: "memory");
    // SMEM freed at block exit: wait until stores have READ it
    asm volatile("cp.async.bulk.wait_group.read 0;" ::: "memory");
}

extern "C" void kernel_launch(void* const* d_in, const int* in_sizes, int n_in,
                              void* d_out, int out_size)
{
    const int*  r_idx = (const int*)d_in[0];
    const char* kv    = (const char*)d_in[1];
    char*       out   = (char*)d_out;

    dim3 grid(2, N_REGIONS);                    // (2, 4096)
    kv_gather_kernel<<<grid, 32>>>(r_idx, kv, out);
}

// round 12
// speedup vs baseline: 1.0338x; 1.0338x over previous
#include <cuda_runtime.h>
#include <cstdint>

// B=4, P2=64, TOPK=16, W2=49, C_KV=512
// r_idx: int32 (B, P2, TOPK) [reference declares int64 but JAX x64-off emits int32]
// kv:    float32 (B, P2, W2, C_KV)
// out:   float32 (B, P2, TOPK, W2, C_KV)
//
// FINAL: direct per-thread gather at the HBM write-stream roofline.
// Region = W2*CKV = 25088 floats = 6272 float4 = 448 threads * 14 float4.
// One block per region (grid=4096). 14 independent LDG.128 in flight per
// thread (front-batched), then 14 evict-first STG.128.
//
// Roofline evidence (7 mechanisms, all ~63.4-64us @ ~74.5% dram_cycles_active):
// per-thread STG, persistent, 3-CTA occupancy, inverted multicast (STG & TMA),
// all-TMA direct, double-depth TMA. Traffic is at the algorithmic floor
// (411MB mandatory write; kv reads L2-resident). ~5.9TB/s is the HBM3e
// write-stream ceiling on this part.

#define B_    4
#define P2_   64
#define TOPK_ 16
#define W2_   49
#define CKV_  512

#define THREADS_    448
#define PER_THREAD_ 14
#define REGION_F4   ((W2_ * CKV_) / 4)      // 6272
#define N_REGIONS   (B_ * P2_ * TOPK_)      // 4096

__global__ void __launch_bounds__(THREADS_, 2) kv_gather_kernel(
    const int*    __restrict__ r_idx,
    const float4* __restrict__ kv,
    float4*       __restrict__ out)
{
    const int region = blockIdx.x;              // 0..4095 = (b, p, k) flattened
    const int b = region >> 10;                 // region / (P2*TOPK)

    int r = __ldg(&r_idx[region]);
    r = min(max(r, 0), P2_ - 1);                // safety clamp (ALU is idle anyway)

    const float4* __restrict__ src = kv  + (long long)(b * P2_ + r) * REGION_F4;
    float4*       __restrict__ dst = out + (long long)region * REGION_F4;

    const int t = threadIdx.x;

    float4 v[PER_THREAD_];
#pragma unroll
    for (int i = 0; i < PER_THREAD_; i++)
        v[i] = __ldg(&src[t + i * THREADS_]);

#pragma unroll
    for (int i = 0; i < PER_THREAD_; i++)
        __stcs(&dst[t + i * THREADS_], v[i]);   // evict-first: keep kv L2-resident
}

extern "C" void kernel_launch(void* const* d_in, const int* in_sizes, int n_in,
                              void* d_out, int out_size)
{
    const int*    r_idx = (const int*)d_in[0];
    const float4* kv    = (const float4*)d_in[1];
    float4*       out   = (float4*)d_out;

    kv_gather_kernel<<<N_REGIONS, THREADS_>>>(r_idx, kv, out);
}